// round 3
// baseline (speedup 1.0000x reference)
#include <cuda_runtime.h>
#include <cuda_bf16.h>

// ---------------- problem constants ----------------
#define BB 32
#define SS 2048
#define UU 512
#define VV 32000
#define G4 (4*UU)          // 2048 gate width

// ---------------- scratch (device globals; no allocs) ----------------
__device__ float g_gates[BB*G4];     // x@W_ih.T + h@W_hh.T partials
__device__ float g_dg[BB*UU];        // ds@w_d.T + coverage@w_g_w.T + w_g_b
__device__ float g_scores[BB*SS];    // raw attention scores
__device__ float g_context[BB*UU];
__device__ float g_mid[BB*UU];       // rnn_output @ w_c.T
__device__ float g_logits[BB*VV];    // mid @ f_c_w.T partials
__device__ float g_pgen[BB];

// ---------------- init: zero accumulators, seed g_dg with bias ----------------
__global__ void init_kernel(const float* __restrict__ w_g_b) {
    int i = blockIdx.x * 256 + threadIdx.x;           // grid covers 1,024,000
    if (i < BB*VV)  g_logits[i] = 0.f;
    if (i < BB*G4)  { g_gates[i] = 0.f; g_scores[i] = 0.f; }
    if (i < BB*UU)  { g_context[i] = 0.f; g_mid[i] = 0.f; g_dg[i] = w_g_b[i & (UU-1)]; }
}

// ---------------- generic M=32 GEMM: out[m,n] += sum_k A[m,k]*W[n,k] ----------
// NTILE=128 cols/block, KC=32 smem stage, k-split over blockIdx.y, atomic epilogue.
#define NT 128
#define KC 32
__global__ void gemm32(const float* __restrict__ A, const float* __restrict__ W,
                       float* __restrict__ out,
                       int lda, int ldw, int N, int kPerBlock)
{
    __shared__ float xs[KC][36];    // [kk][m]  pad 36: float4-aligned rows
    __shared__ float ws[KC][132];   // [kk][n]  pad 132
    const int n0 = blockIdx.x * NT;
    const int k0 = blockIdx.y * kPerBlock;
    const int kEnd = k0 + kPerBlock;
    const int t  = threadIdx.x;
    const int tm = t >> 5;          // 0..7  -> 4 m rows
    const int tn = t & 31;          // 0..31 -> 4 n cols
    float acc[4][4] = {};

    for (int kb = k0; kb < kEnd; kb += KC) {
        #pragma unroll
        for (int i = 0; i < 4; i++) {               // 32k x 32m
            int idx = t + i*256;
            int kk = idx & 31, m = idx >> 5;
            xs[kk][m] = A[m*lda + kb + kk];
        }
        #pragma unroll
        for (int i = 0; i < 16; i++) {              // 32k x 128n
            int idx = t + i*256;
            int kk = idx & 31, n = idx >> 5;
            ws[kk][n] = W[(size_t)(n0 + n)*ldw + kb + kk];
        }
        __syncthreads();
        #pragma unroll
        for (int kk = 0; kk < KC; kk++) {
            float4 xf = *(const float4*)&xs[kk][tm*4];
            float4 wf = *(const float4*)&ws[kk][tn*4];
            float xv[4] = {xf.x, xf.y, xf.z, xf.w};
            float wv[4] = {wf.x, wf.y, wf.z, wf.w};
            #pragma unroll
            for (int a = 0; a < 4; a++)
                #pragma unroll
                for (int c = 0; c < 4; c++)
                    acc[a][c] += xv[a] * wv[c];
        }
        __syncthreads();
    }
    #pragma unroll
    for (int a = 0; a < 4; a++) {
        int m = tm*4 + a;
        #pragma unroll
        for (int c = 0; c < 4; c++)
            atomicAdd(&out[m*N + n0 + tn*4 + c], acc[a][c]);
    }
}

// ---------------- LSTM cell ----------------
__global__ void lstm_kernel(const float* __restrict__ bih, const float* __restrict__ bhh,
                            const float* __restrict__ c0,
                            float* __restrict__ h_out, float* __restrict__ c_out)
{
    int t = blockIdx.x * 256 + threadIdx.x;   // 16384
    int b = t >> 9, u = t & (UU-1);
    const float* gr = &g_gates[b*G4];
    float gi = gr[u]          + bih[u]          + bhh[u];
    float gf = gr[512  + u]   + bih[512  + u]   + bhh[512  + u];
    float gg = gr[1024 + u]   + bih[1024 + u]   + bhh[1024 + u];
    float go = gr[1536 + u]   + bih[1536 + u]   + bhh[1536 + u];
    float si = 1.f / (1.f + expf(-gi));
    float sf = 1.f / (1.f + expf(-gf));
    float so = 1.f / (1.f + expf(-go));
    float cn = sf * c0[t] + si * tanhf(gg);
    c_out[t] = cn;
    h_out[t] = so * tanhf(cn);
}

// ---------------- attention scores (the 17.2 GFLOP kernel) ----------------
// scores[b,s] += sum_{u in tile} V_w[u]*tanh(g_dg[b,u] + enc[b,s,:]@w_e[u,:])
// block: 64 rows (one b) x 256 u-cols, 8x8 micro-tile, K=512 in chunks of 16.
#define RD 64
#define UD 256
#define KD 16
__global__ void attn_scores(const float* __restrict__ enc, const float* __restrict__ w_e,
                            const float* __restrict__ V_w)
{
    __shared__ float es[KD][68];     // [kk][r]
    __shared__ float ws[KD][260];    // [kk][u]
    const int r0 = blockIdx.x * RD;          // global row = b*S + s (64-aligned -> one b)
    const int u0 = blockIdx.y * UD;
    const int b  = r0 >> 11;
    const int t  = threadIdx.x;
    const int ty = t >> 5;    // 0..7  r-group (8 rows)
    const int tx = t & 31;    // 0..31 u-group (4+4 cols, split 128 apart)
    float acc[8][8] = {};

    for (int kb = 0; kb < UU; kb += KD) {
        {   // enc tile: 64r x 16k, one float4 per thread
            int rr = t >> 2, kk4 = (t & 3) * 4;
            float4 v = *(const float4*)&enc[(size_t)(r0 + rr)*UU + kb + kk4];
            es[kk4+0][rr] = v.x; es[kk4+1][rr] = v.y;
            es[kk4+2][rr] = v.z; es[kk4+3][rr] = v.w;
        }
        {   // w_e tile: 256u x 16k
            int kv = (t & 3) * 4;
            #pragma unroll
            for (int p = 0; p < 4; p++) {
                int uu = (t >> 2) + p*64;
                float4 v = *(const float4*)&w_e[(size_t)(u0 + uu)*UU + kb + kv];
                ws[kv+0][uu] = v.x; ws[kv+1][uu] = v.y;
                ws[kv+2][uu] = v.z; ws[kv+3][uu] = v.w;
            }
        }
        __syncthreads();
        #pragma unroll
        for (int kk = 0; kk < KD; kk++) {
            float4 e0 = *(const float4*)&es[kk][ty*8];
            float4 e1 = *(const float4*)&es[kk][ty*8 + 4];
            float4 w0 = *(const float4*)&ws[kk][tx*4];
            float4 w1 = *(const float4*)&ws[kk][128 + tx*4];
            float ev[8] = {e0.x,e0.y,e0.z,e0.w, e1.x,e1.y,e1.z,e1.w};
            float wv[8] = {w0.x,w0.y,w0.z,w0.w, w1.x,w1.y,w1.z,w1.w};
            #pragma unroll
            for (int a = 0; a < 8; a++)
                #pragma unroll
                for (int c = 0; c < 8; c++)
                    acc[a][c] += ev[a] * wv[c];
        }
        __syncthreads();
    }
    // epilogue: tanh + V_w reduce over this u-tile, atomic into scores
    float vw[8], dg[8];
    #pragma unroll
    for (int c = 0; c < 8; c++) {
        int u = u0 + (c < 4 ? tx*4 + c : 128 + tx*4 + (c - 4));
        vw[c] = V_w[u];
        dg[c] = g_dg[b*UU + u];
    }
    #pragma unroll
    for (int a = 0; a < 8; a++) {
        float sc = 0.f;
        #pragma unroll
        for (int c = 0; c < 8; c++)
            sc += vw[c] * tanhf(dg[c] + acc[a][c]);
        atomicAdd(&g_scores[r0 + ty*8 + a], sc);
    }
}

// ---------------- softmax over S per batch ----------------
__global__ void softmax_kernel(float* __restrict__ attn_out) {
    int b = blockIdx.x, t = threadIdx.x;
    __shared__ float red[256];
    const float* sc = &g_scores[b*SS];
    float mx = -1e30f;
    for (int s = t; s < SS; s += 256) mx = fmaxf(mx, sc[s]);
    red[t] = mx; __syncthreads();
    for (int o = 128; o > 0; o >>= 1) { if (t < o) red[t] = fmaxf(red[t], red[t+o]); __syncthreads(); }
    mx = red[0]; __syncthreads();
    float sum = 0.f;
    for (int s = t; s < SS; s += 256) sum += expf(sc[s] - mx);
    red[t] = sum; __syncthreads();
    for (int o = 128; o > 0; o >>= 1) { if (t < o) red[t] += red[t+o]; __syncthreads(); }
    float inv = 1.f / red[0];
    for (int s = t; s < SS; s += 256) attn_out[b*SS + s] = expf(sc[s] - mx) * inv;
}

// ---------------- context = attn @ enc ----------------
__global__ void context_kernel(const float* __restrict__ enc, const float* __restrict__ attn) {
    // grid (32 b, 4 u-chunks, 4 s-chunks), 128 threads (u)
    int b = blockIdx.x, uc = blockIdx.y, scb = blockIdx.z;
    int u = uc*128 + threadIdx.x;
    const float* ap = &attn[b*SS + scb*512];
    const float* ep = &enc[((size_t)b*SS + scb*512)*UU + u];
    float acc = 0.f;
    #pragma unroll 4
    for (int s = 0; s < 512; s++)
        acc += ap[s] * ep[(size_t)s*UU];
    atomicAdd(&g_context[b*UU + u], acc);
}

// ---------------- p_gen ----------------
__global__ void pgen_kernel(const float* __restrict__ x, const float* __restrict__ w_x_w,
                            const float* __restrict__ w_x_b,
                            const float* __restrict__ w_h, const float* __restrict__ w_s,
                            const float* __restrict__ h_o)
{
    int b = blockIdx.x, t = threadIdx.x;
    __shared__ float red[256];
    float s = 0.f;
    for (int v = t; v < VV; v += 256) s += x[(size_t)b*VV + v] * w_x_w[v];
    for (int u = t; u < UU; u += 256) s += g_context[b*UU + u]*w_h[u] + h_o[b*UU + u]*w_s[u];
    red[t] = s; __syncthreads();
    for (int o = 128; o > 0; o >>= 1) { if (t < o) red[t] += red[t+o]; __syncthreads(); }
    if (t == 0) g_pgen[b] = 1.f / (1.f + expf(-(red[0] + w_x_b[0])));
}

// ---------------- finalize: scaled logits + copy_logits ----------------
__global__ void finalize_kernel(const float* __restrict__ f_c_b,
                                float* __restrict__ logits_o, float* __restrict__ copy_o)
{
    int i = blockIdx.x * 256 + threadIdx.x;
    if (i < BB*VV) {
        int b = i / VV, v = i - b*VV;
        logits_o[i] = (g_logits[i] + f_c_b[v]) * g_pgen[b];
    } else if (i < BB*VV + BB*SS) {
        int j = i - BB*VV;
        int b = j >> 11;
        copy_o[j] = g_scores[j] * (1.f - g_pgen[b]);
    }
}

// ---------------- launch ----------------
extern "C" void kernel_launch(void* const* d_in, const int* in_sizes, int n_in,
                              void* d_out, int out_size)
{
    (void)in_sizes; (void)n_in; (void)out_size;
    const float* new_tokens = (const float*)d_in[0];   // (32,1,32000)
    const float* enc        = (const float*)d_in[1];   // (32,2048,512)
    const float* h0         = (const float*)d_in[2];   // (1,32,512)
    const float* c0         = (const float*)d_in[3];
    const float* coverage   = (const float*)d_in[4];   // (32,2048)
    const float* W_ih       = (const float*)d_in[5];   // (2048,32000)
    const float* W_hh       = (const float*)d_in[6];   // (2048,512)
    const float* b_ih       = (const float*)d_in[7];
    const float* b_hh       = (const float*)d_in[8];
    const float* w_d        = (const float*)d_in[9];   // (512,512)
    const float* w_e        = (const float*)d_in[10];  // (512,512)
    const float* w_g_w      = (const float*)d_in[11];  // (512,2048)
    const float* w_g_b      = (const float*)d_in[12];
    const float* V_w        = (const float*)d_in[13];  // (1,512)
    const float* w_c        = (const float*)d_in[14];  // (512,1024)
    const float* f_c_w      = (const float*)d_in[15];  // (32000,512)
    const float* f_c_b      = (const float*)d_in[16];
    const float* w_h        = (const float*)d_in[17];
    const float* w_s        = (const float*)d_in[18];
    const float* w_x_w      = (const float*)d_in[19];  // (1,32000)
    const float* w_x_b      = (const float*)d_in[20];
    // d_in[21] = step (unused)

    float* out      = (float*)d_out;
    float* logits_o = out;                       // 32*32000
    float* attn_o   = out + BB*VV;               // 32*2048
    float* h_o      = attn_o + BB*SS;            // 32*512
    float* c_o      = h_o + BB*UU;               // 32*512
    float* copy_o   = c_o + BB*UU;               // 32*2048

    // Resolve REAL device addresses of __device__ globals (host shadow symbols
    // are NOT valid device pointers — that was the Round-2 bug).
    float *p_gates, *p_dg, *p_mid, *p_logits, *p_context;
    cudaGetSymbolAddress((void**)&p_gates,   g_gates);
    cudaGetSymbolAddress((void**)&p_dg,      g_dg);
    cudaGetSymbolAddress((void**)&p_mid,     g_mid);
    cudaGetSymbolAddress((void**)&p_logits,  g_logits);
    cudaGetSymbolAddress((void**)&p_context, g_context);

    init_kernel<<<4000, 256>>>(w_g_b);
    // gates = x @ W_ih.T  (N=2048, K=32000, 25-way k-split)
    gemm32<<<dim3(16, 25), 256>>>(new_tokens, W_ih, p_gates, 32000, 32000, G4, 1280);
    // gates += h @ W_hh.T
    gemm32<<<dim3(16, 4), 256>>>(h0, W_hh, p_gates, 512, 512, G4, 128);
    lstm_kernel<<<64, 256>>>(b_ih, b_hh, c0, h_o, c_o);
    // g_dg = w_g_b + h_new @ w_d.T + coverage @ w_g_w.T
    gemm32<<<dim3(4, 4), 256>>>(h_o, w_d, p_dg, 512, 512, UU, 128);
    gemm32<<<dim3(4, 4), 256>>>(coverage, w_g_w, p_dg, 2048, 2048, UU, 512);
    // raw scores (fused enc@w_e.T -> tanh -> V_w reduce)
    attn_scores<<<dim3(BB*SS/RD, UU/UD), 256>>>(enc, w_e, V_w);
    softmax_kernel<<<32, 256>>>(attn_o);
    context_kernel<<<dim3(32, 4, 4), 128>>>(enc, attn_o);
    // mid = [h_new, context] @ w_c.T  (two half-K GEMMs into same accumulator)
    gemm32<<<dim3(4, 4), 256>>>(h_o, w_c, p_mid, 512, 1024, UU, 128);
    gemm32<<<dim3(4, 4), 256>>>(p_context, w_c + 512, p_mid, 512, 1024, UU, 128);
    pgen_kernel<<<32, 256>>>(new_tokens, w_x_w, w_x_b, w_h, w_s, h_o);
    // logits_raw = mid @ f_c_w.T  (N=32000, K=512)
    gemm32<<<dim3(250, 1), 256>>>(p_mid, f_c_w, p_logits, 512, 512, VV, 512);
    finalize_kernel<<<(BB*VV + BB*SS + 255)/256, 256>>>(f_c_b, logits_o, copy_o);
}

// round 5
// speedup vs baseline: 2.0952x; 2.0952x over previous
#include <cuda_runtime.h>
#include <cuda_bf16.h>
#include <cstdint>

// ---------------- problem constants ----------------
#define BB 32
#define SS 2048
#define UU 512
#define VV 32000
#define G4 (4*UU)          // 2048 gate width

// ---------------- scratch (device globals; no allocs) ----------------
__device__ float g_gates[BB*G4];
__device__ float g_dg[BB*UU];
__device__ float g_scores[BB*SS];
__device__ float g_context[BB*UU];
__device__ float g_mid[BB*UU];
__device__ float g_logits[BB*VV];
__device__ float g_pgen[BB];

// ---------------- helpers ----------------
__device__ __forceinline__ uint32_t f2tf32(float x) {
    uint32_t u;
    asm("cvt.rna.tf32.f32 %0, %1;" : "=r"(u) : "f"(x));
    return u;
}
__device__ __forceinline__ void mma_tf32(float c[4], const uint32_t a[4],
                                         uint32_t b0, uint32_t b1) {
    asm volatile(
        "mma.sync.aligned.m16n8k8.row.col.f32.tf32.tf32.f32 "
        "{%0,%1,%2,%3},{%4,%5,%6,%7},{%8,%9},{%0,%1,%2,%3};"
        : "+f"(c[0]), "+f"(c[1]), "+f"(c[2]), "+f"(c[3])
        : "r"(a[0]), "r"(a[1]), "r"(a[2]), "r"(a[3]), "r"(b0), "r"(b1));
}
// accurate-for-small-x fast tanh: (e^2x - 1)/(e^2x + 1)
__device__ __forceinline__ float fast_tanh(float x) {
    float e = __expf(2.f * x);
    return __fdividef(e - 1.f, e + 1.f);
}

// ---------------- init ----------------
__global__ void init_kernel(const float* __restrict__ w_g_b) {
    int i = blockIdx.x * 256 + threadIdx.x;
    if (i < BB*VV)  g_logits[i] = 0.f;
    if (i < BB*G4)  { g_gates[i] = 0.f; g_scores[i] = 0.f; }
    if (i < BB*UU)  { g_context[i] = 0.f; g_mid[i] = 0.f; g_dg[i] = w_g_b[i & (UU-1)]; }
}

// ---------------- generic M=32 GEMM (TF32 tensor cores) ----------------
// out[m,n] += sum_k A[m,k]*W[n,k].  N-tile 128/block, KB=32 stage, k-split grid.y.
__global__ __launch_bounds__(256) void gemm32_tc(
    const float* __restrict__ A, const float* __restrict__ W,
    float* __restrict__ out, int lda, int ldw, int N, int kPerBlock)
{
    __shared__ float As[32][36];
    __shared__ float Ws[128][36];
    const int n0 = blockIdx.x * 128;
    const int k0 = blockIdx.y * kPerBlock;
    const int t = threadIdx.x, wid = t >> 5, lane = t & 31;
    const int gid = lane >> 2, tig = lane & 3;
    const int rr = t >> 3, kq = (t & 7) * 4;

    float acc[2][2][4] = {};

    for (int kb = k0; kb < k0 + kPerBlock; kb += 32) {
        {   // A: 32x32, one float4/thread
            float4 v = *(const float4*)&A[(size_t)rr*lda + kb + kq];
            As[rr][kq+0] = __uint_as_float(f2tf32(v.x));
            As[rr][kq+1] = __uint_as_float(f2tf32(v.y));
            As[rr][kq+2] = __uint_as_float(f2tf32(v.z));
            As[rr][kq+3] = __uint_as_float(f2tf32(v.w));
        }
        #pragma unroll
        for (int p = 0; p < 4; p++) {   // W: 128x32, four float4/thread
            int n = rr + p*32;
            float4 v = *(const float4*)&W[(size_t)(n0+n)*ldw + kb + kq];
            Ws[n][kq+0] = __uint_as_float(f2tf32(v.x));
            Ws[n][kq+1] = __uint_as_float(f2tf32(v.y));
            Ws[n][kq+2] = __uint_as_float(f2tf32(v.z));
            Ws[n][kq+3] = __uint_as_float(f2tf32(v.w));
        }
        __syncthreads();
        #pragma unroll
        for (int kk = 0; kk < 32; kk += 8) {
            uint32_t a[2][4];
            #pragma unroll
            for (int mt = 0; mt < 2; mt++) {
                int m = mt*16 + gid;
                a[mt][0] = __float_as_uint(As[m  ][kk+tig]);
                a[mt][1] = __float_as_uint(As[m+8][kk+tig]);
                a[mt][2] = __float_as_uint(As[m  ][kk+tig+4]);
                a[mt][3] = __float_as_uint(As[m+8][kk+tig+4]);
            }
            #pragma unroll
            for (int nt = 0; nt < 2; nt++) {
                int u = wid*16 + nt*8 + gid;
                uint32_t b0 = __float_as_uint(Ws[u][kk+tig]);
                uint32_t b1 = __float_as_uint(Ws[u][kk+tig+4]);
                #pragma unroll
                for (int mt = 0; mt < 2; mt++)
                    mma_tf32(acc[mt][nt], a[mt], b0, b1);
            }
        }
        __syncthreads();
    }
    #pragma unroll
    for (int mt = 0; mt < 2; mt++)
        #pragma unroll
        for (int nt = 0; nt < 2; nt++) {
            int n = n0 + wid*16 + nt*8 + 2*tig;
            int m = mt*16 + gid;
            atomicAdd(&out[(size_t)m*N + n],     acc[mt][nt][0]);
            atomicAdd(&out[(size_t)m*N + n + 1], acc[mt][nt][1]);
            atomicAdd(&out[(size_t)(m+8)*N + n],     acc[mt][nt][2]);
            atomicAdd(&out[(size_t)(m+8)*N + n + 1], acc[mt][nt][3]);
        }
}

// ---------------- LSTM cell ----------------
__global__ void lstm_kernel(const float* __restrict__ bih, const float* __restrict__ bhh,
                            const float* __restrict__ c0,
                            float* __restrict__ h_out, float* __restrict__ c_out)
{
    int t = blockIdx.x * 256 + threadIdx.x;
    int b = t >> 9, u = t & (UU-1);
    const float* gr = &g_gates[b*G4];
    float gi = gr[u]        + bih[u]        + bhh[u];
    float gf = gr[512+u]    + bih[512+u]    + bhh[512+u];
    float gg = gr[1024+u]   + bih[1024+u]   + bhh[1024+u];
    float go = gr[1536+u]   + bih[1536+u]   + bhh[1536+u];
    float si = 1.f / (1.f + expf(-gi));
    float sf = 1.f / (1.f + expf(-gf));
    float so = 1.f / (1.f + expf(-go));
    float cn = sf * c0[t] + si * tanhf(gg);
    c_out[t] = cn;
    h_out[t] = so * tanhf(cn);
}

// ---------------- attention scores (TF32 tensor cores) ----------------
// scores[b,s] += sum_u V_w[u]*tanh(g_dg[b,u] + enc[b,s,:]@w_e[u,:])
// block: 64 s-rows x 256 u-cols, K=512 in 32-chunks. 8 warps = 2(m) x 4(n).
__global__ __launch_bounds__(256) void attn_scores_tc(
    const float* __restrict__ enc, const float* __restrict__ w_e,
    const float* __restrict__ V_w)
{
    __shared__ float As[64][36];     // enc tile  [s][k]
    __shared__ float Ws[256][36];    // w_e tile  [u][k]
    const int r0 = blockIdx.x * 64;
    const int u0 = blockIdx.y * 256;
    const int b  = r0 >> 11;
    const int t = threadIdx.x, wid = t >> 5, lane = t & 31;
    const int gid = lane >> 2, tig = lane & 3;
    const int warp_m = wid >> 2;     // 0..1 -> 32 rows
    const int warp_n = wid & 3;      // 0..3 -> 64 cols
    const int rr = t >> 3, kq = (t & 7) * 4;

    float acc[2][8][4] = {};

    for (int kb = 0; kb < UU; kb += 32) {
        #pragma unroll
        for (int p = 0; p < 2; p++) {   // enc 64x32
            int r = rr + p*32;
            float4 v = *(const float4*)&enc[(size_t)(r0+r)*UU + kb + kq];
            As[r][kq+0] = __uint_as_float(f2tf32(v.x));
            As[r][kq+1] = __uint_as_float(f2tf32(v.y));
            As[r][kq+2] = __uint_as_float(f2tf32(v.z));
            As[r][kq+3] = __uint_as_float(f2tf32(v.w));
        }
        #pragma unroll
        for (int p = 0; p < 8; p++) {   // w_e 256x32
            int u = rr + p*32;
            float4 v = *(const float4*)&w_e[(size_t)(u0+u)*UU + kb + kq];
            Ws[u][kq+0] = __uint_as_float(f2tf32(v.x));
            Ws[u][kq+1] = __uint_as_float(f2tf32(v.y));
            Ws[u][kq+2] = __uint_as_float(f2tf32(v.z));
            Ws[u][kq+3] = __uint_as_float(f2tf32(v.w));
        }
        __syncthreads();
        #pragma unroll
        for (int kk = 0; kk < 32; kk += 8) {
            uint32_t a[2][4];
            #pragma unroll
            for (int mt = 0; mt < 2; mt++) {
                int m = warp_m*32 + mt*16 + gid;
                a[mt][0] = __float_as_uint(As[m  ][kk+tig]);
                a[mt][1] = __float_as_uint(As[m+8][kk+tig]);
                a[mt][2] = __float_as_uint(As[m  ][kk+tig+4]);
                a[mt][3] = __float_as_uint(As[m+8][kk+tig+4]);
            }
            #pragma unroll
            for (int nt = 0; nt < 8; nt++) {
                int u = warp_n*64 + nt*8 + gid;
                uint32_t b0 = __float_as_uint(Ws[u][kk+tig]);
                uint32_t b1 = __float_as_uint(Ws[u][kk+tig+4]);
                #pragma unroll
                for (int mt = 0; mt < 2; mt++)
                    mma_tf32(acc[mt][nt], a[mt], b0, b1);
            }
        }
        __syncthreads();
    }

    // epilogue: tanh + V_w reduce over this warp's 64 u, quad-shuffle, atomic
    float rowsum[2][2] = {};   // [mt][half]
    #pragma unroll
    for (int nt = 0; nt < 8; nt++) {
        int u = u0 + warp_n*64 + nt*8 + 2*tig;
        float vw0 = V_w[u],   dg0 = g_dg[b*UU + u];
        float vw1 = V_w[u+1], dg1 = g_dg[b*UU + u + 1];
        #pragma unroll
        for (int mt = 0; mt < 2; mt++) {
            rowsum[mt][0] += vw0*fast_tanh(dg0 + acc[mt][nt][0])
                           + vw1*fast_tanh(dg1 + acc[mt][nt][1]);
            rowsum[mt][1] += vw0*fast_tanh(dg0 + acc[mt][nt][2])
                           + vw1*fast_tanh(dg1 + acc[mt][nt][3]);
        }
    }
    #pragma unroll
    for (int mt = 0; mt < 2; mt++)
        #pragma unroll
        for (int h = 0; h < 2; h++) {
            float s = rowsum[mt][h];
            s += __shfl_xor_sync(0xffffffffu, s, 1);
            s += __shfl_xor_sync(0xffffffffu, s, 2);
            if (tig == 0) {
                int row = warp_m*32 + mt*16 + h*8 + gid;
                atomicAdd(&g_scores[r0 + row], s);
            }
        }
}

// ---------------- softmax over S per batch ----------------
__global__ void softmax_kernel(float* __restrict__ attn_out) {
    int b = blockIdx.x, t = threadIdx.x;
    __shared__ float red[256];
    const float* sc = &g_scores[b*SS];
    float mx = -1e30f;
    for (int s = t; s < SS; s += 256) mx = fmaxf(mx, sc[s]);
    red[t] = mx; __syncthreads();
    for (int o = 128; o > 0; o >>= 1) { if (t < o) red[t] = fmaxf(red[t], red[t+o]); __syncthreads(); }
    mx = red[0]; __syncthreads();
    float sum = 0.f;
    for (int s = t; s < SS; s += 256) sum += expf(sc[s] - mx);
    red[t] = sum; __syncthreads();
    for (int o = 128; o > 0; o >>= 1) { if (t < o) red[t] += red[t+o]; __syncthreads(); }
    float inv = 1.f / red[0];
    for (int s = t; s < SS; s += 256) attn_out[b*SS + s] = expf(sc[s] - mx) * inv;
}

// ---------------- context = attn @ enc ----------------
__global__ void context_kernel(const float* __restrict__ enc, const float* __restrict__ attn) {
    int b = blockIdx.x, uc = blockIdx.y, scb = blockIdx.z;
    int u = uc*128 + threadIdx.x;
    const float* ap = &attn[b*SS + scb*512];
    const float* ep = &enc[((size_t)b*SS + scb*512)*UU + u];
    float acc = 0.f;
    #pragma unroll 4
    for (int s = 0; s < 512; s++)
        acc += ap[s] * ep[(size_t)s*UU];
    atomicAdd(&g_context[b*UU + u], acc);
}

// ---------------- p_gen ----------------
__global__ void pgen_kernel(const float* __restrict__ x, const float* __restrict__ w_x_w,
                            const float* __restrict__ w_x_b,
                            const float* __restrict__ w_h, const float* __restrict__ w_s,
                            const float* __restrict__ h_o)
{
    int b = blockIdx.x, t = threadIdx.x;
    __shared__ float red[256];
    float s = 0.f;
    for (int v = t; v < VV; v += 256) s += x[(size_t)b*VV + v] * w_x_w[v];
    for (int u = t; u < UU; u += 256) s += g_context[b*UU + u]*w_h[u] + h_o[b*UU + u]*w_s[u];
    red[t] = s; __syncthreads();
    for (int o = 128; o > 0; o >>= 1) { if (t < o) red[t] += red[t+o]; __syncthreads(); }
    if (t == 0) g_pgen[b] = 1.f / (1.f + expf(-(red[0] + w_x_b[0])));
}

// ---------------- finalize ----------------
__global__ void finalize_kernel(const float* __restrict__ f_c_b,
                                float* __restrict__ logits_o, float* __restrict__ copy_o)
{
    int i = blockIdx.x * 256 + threadIdx.x;
    if (i < BB*VV) {
        int b = i / VV, v = i - b*VV;
        logits_o[i] = (g_logits[i] + f_c_b[v]) * g_pgen[b];
    } else if (i < BB*VV + BB*SS) {
        int j = i - BB*VV;
        int b = j >> 11;
        copy_o[j] = g_scores[j] * (1.f - g_pgen[b]);
    }
}

// ---------------- launch ----------------
extern "C" void kernel_launch(void* const* d_in, const int* in_sizes, int n_in,
                              void* d_out, int out_size)
{
    (void)in_sizes; (void)n_in; (void)out_size;
    const float* new_tokens = (const float*)d_in[0];
    const float* enc        = (const float*)d_in[1];
    const float* h0         = (const float*)d_in[2];
    const float* c0         = (const float*)d_in[3];
    const float* coverage   = (const float*)d_in[4];
    const float* W_ih       = (const float*)d_in[5];
    const float* W_hh       = (const float*)d_in[6];
    const float* b_ih       = (const float*)d_in[7];
    const float* b_hh       = (const float*)d_in[8];
    const float* w_d        = (const float*)d_in[9];
    const float* w_e        = (const float*)d_in[10];
    const float* w_g_w      = (const float*)d_in[11];
    const float* w_g_b      = (const float*)d_in[12];
    const float* V_w        = (const float*)d_in[13];
    const float* w_c        = (const float*)d_in[14];
    const float* f_c_w      = (const float*)d_in[15];
    const float* f_c_b      = (const float*)d_in[16];
    const float* w_h        = (const float*)d_in[17];
    const float* w_s        = (const float*)d_in[18];
    const float* w_x_w      = (const float*)d_in[19];
    const float* w_x_b      = (const float*)d_in[20];

    float* out      = (float*)d_out;
    float* logits_o = out;
    float* attn_o   = out + BB*VV;
    float* h_o      = attn_o + BB*SS;
    float* c_o      = h_o + BB*UU;
    float* copy_o   = c_o + BB*UU;

    float *p_gates, *p_dg, *p_mid, *p_logits, *p_context;
    cudaGetSymbolAddress((void**)&p_gates,   g_gates);
    cudaGetSymbolAddress((void**)&p_dg,      g_dg);
    cudaGetSymbolAddress((void**)&p_mid,     g_mid);
    cudaGetSymbolAddress((void**)&p_logits,  g_logits);
    cudaGetSymbolAddress((void**)&p_context, g_context);

    init_kernel<<<4000, 256>>>(w_g_b);
    // gates = x @ W_ih.T  (N=2048, K=32000, 25-way k-split)
    gemm32_tc<<<dim3(16, 25), 256>>>(new_tokens, W_ih, p_gates, 32000, 32000, G4, 1280);
    // gates += h @ W_hh.T
    gemm32_tc<<<dim3(16, 4), 256>>>(h0, W_hh, p_gates, 512, 512, G4, 128);
    lstm_kernel<<<64, 256>>>(b_ih, b_hh, c0, h_o, c_o);
    // g_dg = w_g_b + h_new @ w_d.T + coverage @ w_g_w.T
    gemm32_tc<<<dim3(4, 4), 256>>>(h_o, w_d, p_dg, 512, 512, UU, 128);
    gemm32_tc<<<dim3(4, 4), 256>>>(coverage, w_g_w, p_dg, 2048, 2048, UU, 512);
    // raw scores (fused enc@w_e.T -> tanh -> V_w reduce), TF32 MMA
    attn_scores_tc<<<dim3(BB*SS/64, 2), 256>>>(enc, w_e, V_w);
    softmax_kernel<<<32, 256>>>(attn_o);
    context_kernel<<<dim3(32, 4, 4), 128>>>(enc, attn_o);
    // mid = [h_new, context] @ w_c.T
    gemm32_tc<<<dim3(4, 4), 256>>>(h_o, w_c, p_mid, 512, 1024, UU, 128);
    gemm32_tc<<<dim3(4, 4), 256>>>(p_context, w_c + 512, p_mid, 512, 1024, UU, 128);
    pgen_kernel<<<32, 256>>>(new_tokens, w_x_w, w_x_b, w_h, w_s, h_o);
    // logits_raw = mid @ f_c_w.T
    gemm32_tc<<<dim3(250, 1), 256>>>(p_mid, f_c_w, p_logits, 512, 512, VV, 512);
    finalize_kernel<<<(BB*VV + BB*SS + 255)/256, 256>>>(f_c_b, logits_o, copy_o);
}

// round 11
// speedup vs baseline: 2.1011x; 1.0028x over previous
#include <cuda_runtime.h>
#include <cuda_bf16.h>
#include <cstdint>

// ---------------- problem constants ----------------
#define BB 32
#define SS 2048
#define UU 512
#define VV 32000
#define G4 (4*UU)          // 2048 gate width

// ---------------- scratch (device globals; no allocs) ----------------
__device__ float g_gates[BB*G4];
__device__ float g_dg[BB*UU];
__device__ float g_scores[BB*SS];
__device__ float g_context[BB*UU];
__device__ float g_mid[BB*UU];
__device__ float g_logits[BB*VV];
__device__ float g_pgen[BB];

// ---------------- helpers ----------------
__device__ __forceinline__ uint32_t f2tf32(float x) {
    uint32_t u;
    asm("cvt.rna.tf32.f32 %0, %1;" : "=r"(u) : "f"(x));
    return u;
}
__device__ __forceinline__ float4 cvt4(float4 v) {
    return make_float4(__uint_as_float(f2tf32(v.x)), __uint_as_float(f2tf32(v.y)),
                       __uint_as_float(f2tf32(v.z)), __uint_as_float(f2tf32(v.w)));
}
__device__ __forceinline__ void mma_tf32(float c[4], const uint32_t a[4],
                                         uint32_t b0, uint32_t b1) {
    asm volatile(
        "mma.sync.aligned.m16n8k8.row.col.f32.tf32.tf32.f32 "
        "{%0,%1,%2,%3},{%4,%5,%6,%7},{%8,%9},{%0,%1,%2,%3};"
        : "+f"(c[0]), "+f"(c[1]), "+f"(c[2]), "+f"(c[3])
        : "r"(a[0]), "r"(a[1]), "r"(a[2]), "r"(a[3]), "r"(b0), "r"(b1));
}
// accurate-for-small-x fast tanh: (e^2x - 1)/(e^2x + 1)
__device__ __forceinline__ float fast_tanh(float x) {
    float e = __expf(2.f * x);
    return __fdividef(e - 1.f, e + 1.f);
}

// ---------------- init ----------------
__global__ void init_kernel(const float* __restrict__ w_g_b) {
    int i = blockIdx.x * 256 + threadIdx.x;
    if (i < BB*VV)  g_logits[i] = 0.f;
    if (i < BB*G4)  { g_gates[i] = 0.f; g_scores[i] = 0.f; }
    if (i < BB*UU)  { g_context[i] = 0.f; g_mid[i] = 0.f; g_dg[i] = w_g_b[i & (UU-1)]; }
}

// ---------------- generic M=32 GEMM (TF32 tensor cores) ----------------
__global__ __launch_bounds__(256) void gemm32_tc(
    const float* __restrict__ A, const float* __restrict__ W,
    float* __restrict__ out, int lda, int ldw, int N, int kPerBlock)
{
    __shared__ float As[32][36];
    __shared__ float Ws[128][36];
    const int n0 = blockIdx.x * 128;
    const int k0 = blockIdx.y * kPerBlock;
    const int t = threadIdx.x, wid = t >> 5, lane = t & 31;
    const int gid = lane >> 2, tig = lane & 3;
    const int rr = t >> 3, kq = (t & 7) * 4;

    float acc[2][2][4] = {};

    for (int kb = k0; kb < k0 + kPerBlock; kb += 32) {
        {
            float4 v = *(const float4*)&A[(size_t)rr*lda + kb + kq];
            *(float4*)&As[rr][kq] = cvt4(v);
        }
        #pragma unroll
        for (int p = 0; p < 4; p++) {
            int n = rr + p*32;
            float4 v = *(const float4*)&W[(size_t)(n0+n)*ldw + kb + kq];
            *(float4*)&Ws[n][kq] = cvt4(v);
        }
        __syncthreads();
        #pragma unroll
        for (int kk = 0; kk < 32; kk += 8) {
            uint32_t a[2][4];
            #pragma unroll
            for (int mt = 0; mt < 2; mt++) {
                int m = mt*16 + gid;
                a[mt][0] = __float_as_uint(As[m  ][kk+tig]);
                a[mt][1] = __float_as_uint(As[m+8][kk+tig]);
                a[mt][2] = __float_as_uint(As[m  ][kk+tig+4]);
                a[mt][3] = __float_as_uint(As[m+8][kk+tig+4]);
            }
            #pragma unroll
            for (int nt = 0; nt < 2; nt++) {
                int u = wid*16 + nt*8 + gid;
                uint32_t b0 = __float_as_uint(Ws[u][kk+tig]);
                uint32_t b1 = __float_as_uint(Ws[u][kk+tig+4]);
                #pragma unroll
                for (int mt = 0; mt < 2; mt++)
                    mma_tf32(acc[mt][nt], a[mt], b0, b1);
            }
        }
        __syncthreads();
    }
    #pragma unroll
    for (int mt = 0; mt < 2; mt++)
        #pragma unroll
        for (int nt = 0; nt < 2; nt++) {
            int n = n0 + wid*16 + nt*8 + 2*tig;
            int m = mt*16 + gid;
            atomicAdd(&out[(size_t)m*N + n],     acc[mt][nt][0]);
            atomicAdd(&out[(size_t)m*N + n + 1], acc[mt][nt][1]);
            atomicAdd(&out[(size_t)(m+8)*N + n],     acc[mt][nt][2]);
            atomicAdd(&out[(size_t)(m+8)*N + n + 1], acc[mt][nt][3]);
        }
}

// ---------------- LSTM cell ----------------
__global__ void lstm_kernel(const float* __restrict__ bih, const float* __restrict__ bhh,
                            const float* __restrict__ c0,
                            float* __restrict__ h_out, float* __restrict__ c_out)
{
    int t = blockIdx.x * 256 + threadIdx.x;
    int b = t >> 9, u = t & (UU-1);
    const float* gr = &g_gates[b*G4];
    float gi = gr[u]        + bih[u]        + bhh[u];
    float gf = gr[512+u]    + bih[512+u]    + bhh[512+u];
    float gg = gr[1024+u]   + bih[1024+u]   + bhh[1024+u];
    float go = gr[1536+u]   + bih[1536+u]   + bhh[1536+u];
    float si = 1.f / (1.f + expf(-gi));
    float sf = 1.f / (1.f + expf(-gf));
    float so = 1.f / (1.f + expf(-go));
    float cn = sf * c0[t] + si * tanhf(gg);
    c_out[t] = cn;
    h_out[t] = so * tanhf(cn);
}

// ---------------- attention scores v2: 128x256 tile, double-buffered ----------
// scores[b,s] += sum_u V_w[u]*tanh(g_dg[b,u] + enc[b,s,:]@w_e[u,:])
// 512 thr = 16 warps (4m x 4n). Dyn smem: 2 stages x (As 128x36 + Ws 256x36).
#define AT_STAGE 13824   // floats per stage (4608 + 9216)
__global__ __launch_bounds__(512) void attn_scores_tc2(
    const float* __restrict__ enc, const float* __restrict__ w_e,
    const float* __restrict__ V_w)
{
    extern __shared__ float sm[];
    const int u0 = blockIdx.x * 256;     // u-half (grid.x = 2, fastest -> L2 pair)
    const int r0 = blockIdx.y * 128;     // row tile (one b per block)
    const int b  = r0 >> 11;
    const int t = threadIdx.x, wid = t >> 5, lane = t & 31;
    const int gid = lane >> 2, tig = lane & 3;
    const int warp_m = wid & 3;          // 4 groups of 32 rows
    const int warp_n = wid >> 2;         // 4 groups of 64 u
    const int rA = t >> 2, kA = (t & 3) * 8;     // As loader: 128r x 32k
    const int rW = t >> 1, kW = (t & 1) * 16;    // Ws loader: 256u x 32k

    const float* encp = enc + (size_t)(r0 + rA)*UU + kA;
    const float* wep  = w_e + (size_t)(u0 + rW)*UU + kW;

    float acc[2][8][4] = {};
    float4 sA0, sA1, sW0, sW1, sW2, sW3;

    // prologue: stage 0 -> buf 0
    sA0 = *(const float4*)(encp);     sA1 = *(const float4*)(encp + 4);
    sW0 = *(const float4*)(wep);      sW1 = *(const float4*)(wep + 4);
    sW2 = *(const float4*)(wep + 8);  sW3 = *(const float4*)(wep + 12);
    {
        float* Ad = sm;  float* Wd = sm + 4608;
        *(float4*)&Ad[rA*36 + kA]      = cvt4(sA0);
        *(float4*)&Ad[rA*36 + kA + 4]  = cvt4(sA1);
        *(float4*)&Wd[rW*36 + kW]      = cvt4(sW0);
        *(float4*)&Wd[rW*36 + kW + 4]  = cvt4(sW1);
        *(float4*)&Wd[rW*36 + kW + 8]  = cvt4(sW2);
        *(float4*)&Wd[rW*36 + kW + 12] = cvt4(sW3);
    }
    __syncthreads();

    #pragma unroll 2
    for (int st = 0; st < 16; st++) {
        if (st < 15) {   // prefetch next stage into registers
            int kb = (st + 1) * 32;
            sA0 = *(const float4*)(encp + kb);     sA1 = *(const float4*)(encp + kb + 4);
            sW0 = *(const float4*)(wep + kb);      sW1 = *(const float4*)(wep + kb + 4);
            sW2 = *(const float4*)(wep + kb + 8);  sW3 = *(const float4*)(wep + kb + 12);
        }
        const float* As = sm + (st & 1) * AT_STAGE;
        const float* Ws = As + 4608;
        #pragma unroll
        for (int kk = 0; kk < 32; kk += 8) {
            uint32_t a[2][4];
            #pragma unroll
            for (int mt = 0; mt < 2; mt++) {
                int m = warp_m*32 + mt*16 + gid;
                a[mt][0] = __float_as_uint(As[(m  )*36 + kk + tig]);
                a[mt][1] = __float_as_uint(As[(m+8)*36 + kk + tig]);
                a[mt][2] = __float_as_uint(As[(m  )*36 + kk + tig + 4]);
                a[mt][3] = __float_as_uint(As[(m+8)*36 + kk + tig + 4]);
            }
            #pragma unroll
            for (int nt = 0; nt < 8; nt++) {
                int u = warp_n*64 + nt*8 + gid;
                uint32_t b0 = __float_as_uint(Ws[u*36 + kk + tig]);
                uint32_t b1 = __float_as_uint(Ws[u*36 + kk + tig + 4]);
                #pragma unroll
                for (int mt = 0; mt < 2; mt++)
                    mma_tf32(acc[mt][nt], a[mt], b0, b1);
            }
        }
        if (st < 15) {   // store prefetched stage into the other buffer
            float* Ad = sm + ((st + 1) & 1) * AT_STAGE;
            float* Wd = Ad + 4608;
            *(float4*)&Ad[rA*36 + kA]      = cvt4(sA0);
            *(float4*)&Ad[rA*36 + kA + 4]  = cvt4(sA1);
            *(float4*)&Wd[rW*36 + kW]      = cvt4(sW0);
            *(float4*)&Wd[rW*36 + kW + 4]  = cvt4(sW1);
            *(float4*)&Wd[rW*36 + kW + 8]  = cvt4(sW2);
            *(float4*)&Wd[rW*36 + kW + 12] = cvt4(sW3);
            __syncthreads();
        }
    }

    // epilogue: tanh + V_w reduce over this warp's 64 u, quad-shuffle, atomic
    float rowsum[2][2] = {};
    #pragma unroll
    for (int nt = 0; nt < 8; nt++) {
        int u = u0 + warp_n*64 + nt*8 + 2*tig;
        float vw0 = V_w[u],   dg0 = g_dg[b*UU + u];
        float vw1 = V_w[u+1], dg1 = g_dg[b*UU + u + 1];
        #pragma unroll
        for (int mt = 0; mt < 2; mt++) {
            rowsum[mt][0] += vw0*fast_tanh(dg0 + acc[mt][nt][0])
                           + vw1*fast_tanh(dg1 + acc[mt][nt][1]);
            rowsum[mt][1] += vw0*fast_tanh(dg0 + acc[mt][nt][2])
                           + vw1*fast_tanh(dg1 + acc[mt][nt][3]);
        }
    }
    #pragma unroll
    for (int mt = 0; mt < 2; mt++)
        #pragma unroll
        for (int h = 0; h < 2; h++) {
            float s = rowsum[mt][h];
            s += __shfl_xor_sync(0xffffffffu, s, 1);
            s += __shfl_xor_sync(0xffffffffu, s, 2);
            if (tig == 0) {
                int row = warp_m*32 + mt*16 + h*8 + gid;
                atomicAdd(&g_scores[r0 + row], s);
            }
        }
}

// ---------------- softmax over S per batch ----------------
__global__ void softmax_kernel(float* __restrict__ attn_out) {
    int b = blockIdx.x, t = threadIdx.x;
    __shared__ float red[256];
    const float* sc = &g_scores[b*SS];
    float mx = -1e30f;
    for (int s = t; s < SS; s += 256) mx = fmaxf(mx, sc[s]);
    red[t] = mx; __syncthreads();
    for (int o = 128; o > 0; o >>= 1) { if (t < o) red[t] = fmaxf(red[t], red[t+o]); __syncthreads(); }
    mx = red[0]; __syncthreads();
    float sum = 0.f;
    for (int s = t; s < SS; s += 256) sum += expf(sc[s] - mx);
    red[t] = sum; __syncthreads();
    for (int o = 128; o > 0; o >>= 1) { if (t < o) red[t] += red[t+o]; __syncthreads(); }
    float inv = 1.f / red[0];
    for (int s = t; s < SS; s += 256) attn_out[b*SS + s] = expf(sc[s] - mx) * inv;
}

// ---------------- context = attn @ enc ----------------
__global__ void context_kernel(const float* __restrict__ enc, const float* __restrict__ attn) {
    int b = blockIdx.x, uc = blockIdx.y, scb = blockIdx.z;
    int u = uc*128 + threadIdx.x;
    const float* ap = &attn[b*SS + scb*512];
    const float* ep = &enc[((size_t)b*SS + scb*512)*UU + u];
    float acc = 0.f;
    #pragma unroll 4
    for (int s = 0; s < 512; s++)
        acc += ap[s] * ep[(size_t)s*UU];
    atomicAdd(&g_context[b*UU + u], acc);
}

// ---------------- p_gen ----------------
__global__ void pgen_kernel(const float* __restrict__ x, const float* __restrict__ w_x_w,
                            const float* __restrict__ w_x_b,
                            const float* __restrict__ w_h, const float* __restrict__ w_s,
                            const float* __restrict__ h_o)
{
    int b = blockIdx.x, t = threadIdx.x;
    __shared__ float red[256];
    float s = 0.f;
    for (int v = t; v < VV; v += 256) s += x[(size_t)b*VV + v] * w_x_w[v];
    for (int u = t; u < UU; u += 256) s += g_context[b*UU + u]*w_h[u] + h_o[b*UU + u]*w_s[u];
    red[t] = s; __syncthreads();
    for (int o = 128; o > 0; o >>= 1) { if (t < o) red[t] += red[t+o]; __syncthreads(); }
    if (t == 0) g_pgen[b] = 1.f / (1.f + expf(-(red[0] + w_x_b[0])));
}

// ---------------- finalize ----------------
__global__ void finalize_kernel(const float* __restrict__ f_c_b,
                                float* __restrict__ logits_o, float* __restrict__ copy_o)
{
    int i = blockIdx.x * 256 + threadIdx.x;
    if (i < BB*VV) {
        int b = i / VV, v = i - b*VV;
        logits_o[i] = (g_logits[i] + f_c_b[v]) * g_pgen[b];
    } else if (i < BB*VV + BB*SS) {
        int j = i - BB*VV;
        int b = j >> 11;
        copy_o[j] = g_scores[j] * (1.f - g_pgen[b]);
    }
}

// ---------------- launch ----------------
extern "C" void kernel_launch(void* const* d_in, const int* in_sizes, int n_in,
                              void* d_out, int out_size)
{
    (void)in_sizes; (void)n_in; (void)out_size;
    const float* new_tokens = (const float*)d_in[0];
    const float* enc        = (const float*)d_in[1];
    const float* h0         = (const float*)d_in[2];
    const float* c0         = (const float*)d_in[3];
    const float* coverage   = (const float*)d_in[4];
    const float* W_ih       = (const float*)d_in[5];
    const float* W_hh       = (const float*)d_in[6];
    const float* b_ih       = (const float*)d_in[7];
    const float* b_hh       = (const float*)d_in[8];
    const float* w_d        = (const float*)d_in[9];
    const float* w_e        = (const float*)d_in[10];
    const float* w_g_w      = (const float*)d_in[11];
    const float* w_g_b      = (const float*)d_in[12];
    const float* V_w        = (const float*)d_in[13];
    const float* w_c        = (const float*)d_in[14];
    const float* f_c_w      = (const float*)d_in[15];
    const float* f_c_b      = (const float*)d_in[16];
    const float* w_h        = (const float*)d_in[17];
    const float* w_s        = (const float*)d_in[18];
    const float* w_x_w      = (const float*)d_in[19];
    const float* w_x_b      = (const float*)d_in[20];

    float* out      = (float*)d_out;
    float* logits_o = out;
    float* attn_o   = out + BB*VV;
    float* h_o      = attn_o + BB*SS;
    float* c_o      = h_o + BB*UU;
    float* copy_o   = c_o + BB*UU;

    float *p_gates, *p_dg, *p_mid, *p_logits, *p_context;
    cudaGetSymbolAddress((void**)&p_gates,   g_gates);
    cudaGetSymbolAddress((void**)&p_dg,      g_dg);
    cudaGetSymbolAddress((void**)&p_mid,     g_mid);
    cudaGetSymbolAddress((void**)&p_logits,  g_logits);
    cudaGetSymbolAddress((void**)&p_context, g_context);

    // Unconditional (no static guard — harness forbids call-count-dependent
    // behavior). Host-side attribute set; not a stream op, capture-safe.
    cudaFuncSetAttribute(attn_scores_tc2,
                         cudaFuncAttributeMaxDynamicSharedMemorySize,
                         2 * AT_STAGE * (int)sizeof(float));

    init_kernel<<<4000, 256>>>(w_g_b);
    // gates = x @ W_ih.T  (N=2048, K=32000, 25-way k-split)
    gemm32_tc<<<dim3(16, 25), 256>>>(new_tokens, W_ih, p_gates, 32000, 32000, G4, 1280);
    // gates += h @ W_hh.T
    gemm32_tc<<<dim3(16, 4), 256>>>(h0, W_hh, p_gates, 512, 512, G4, 128);
    lstm_kernel<<<64, 256>>>(b_ih, b_hh, c0, h_o, c_o);
    // g_dg = w_g_b + h_new @ w_d.T + coverage @ w_g_w.T
    gemm32_tc<<<dim3(4, 4), 256>>>(h_o, w_d, p_dg, 512, 512, UU, 128);
    gemm32_tc<<<dim3(4, 4), 256>>>(coverage, w_g_w, p_dg, 2048, 2048, UU, 512);
    // raw scores (fused enc@w_e.T -> tanh -> V_w reduce), TF32 MMA v2
    attn_scores_tc2<<<dim3(2, BB*SS/128), 512, 2*AT_STAGE*sizeof(float)>>>(enc, w_e, V_w);
    softmax_kernel<<<32, 256>>>(attn_o);
    context_kernel<<<dim3(32, 4, 4), 128>>>(enc, attn_o);
    // mid = [h_new, context] @ w_c.T
    gemm32_tc<<<dim3(4, 4), 256>>>(h_o, w_c, p_mid, 512, 1024, UU, 128);
    gemm32_tc<<<dim3(4, 4), 256>>>(p_context, w_c + 512, p_mid, 512, 1024, UU, 128);
    pgen_kernel<<<32, 256>>>(new_tokens, w_x_w, w_x_b, w_h, w_s, h_o);
    // logits_raw = mid @ f_c_w.T
    gemm32_tc<<<dim3(250, 1), 256>>>(p_mid, f_c_w, p_logits, 512, 512, VV, 512);
    finalize_kernel<<<(BB*VV + BB*SS + 255)/256, 256>>>(f_c_b, logits_o, copy_o);
}